// round 17
// baseline (speedup 1.0000x reference)
#include <cuda_runtime.h>
#include <cuda_bf16.h>
#include <cuda_fp16.h>
#include <math.h>
#include <stdint.h>

#define T_TOK   4096
#define D_MODEL 2048
#define FF      8192
#define NE      8
#define PM      40
#define MAXT    40
#define KT1     32
#define NT1     64
#define KT2     128
#define NT2     16
#define BLKA    16384   // fp16 plane: 128 rows x 128B
#define NBLK    152     // persistent blocks

// ---------------- scratch ----------------
__device__ int   g_idx[T_TOK];
__device__ float g_w[T_TOK];
__device__ int   g_order[T_TOK];
__device__ int   g_off[NE + 1];
__device__ int   g_ptok[PM * 128];
__device__ int   g_tile_e[MAXT];
__device__ int   g_tile_gt[MAXT];
__device__ int   g_tile_m64[MAXT];
__device__ int   g_ntiles;
__device__ int   g_work1;
__device__ int   g_work2;
__device__ uint32_t g_f1[NT1 * NE * KT1];   // 16384 unit-ready flags (gemm1/W1)
__device__ uint32_t g_f2[NT2 * NE * KT2];   // 16384 unit-ready flags (gemm2/W2)

__device__ __align__(128) char g_A [(size_t)PM * KT1 * BLKA];
__device__ __align__(128) char g_B1[(size_t)NE * NT1 * KT1 * BLKA];
__device__ __align__(128) char g_B2[(size_t)NE * NT2 * KT2 * BLKA];
__device__ __align__(128) char g_H [(size_t)PM * KT2 * BLKA];

// ---------------- helpers ----------------
__device__ __forceinline__ uint32_t s2u(const void* p) {
    uint32_t a;
    asm("{ .reg .u64 t; cvta.to.shared.u64 t, %1; cvt.u32.u64 %0, t; }" : "=r"(a) : "l"(p));
    return a;
}
__device__ __forceinline__ uint32_t pack2h(float a, float b) {
    __half2 t = __floats2half2_rn(a, b);
    return *(uint32_t*)&t;
}
__device__ __forceinline__ float gelu_exact(float v) {
    return 0.5f * v * (1.0f + erff(v * 0.70710678118654752440f));
}
__device__ __forceinline__ void mbar_init(uint32_t m, uint32_t c) {
    asm volatile("mbarrier.init.shared::cta.b64 [%0], %1;" :: "r"(m), "r"(c) : "memory");
}
__device__ __forceinline__ void mbar_arrive(uint32_t m) {
    asm volatile("mbarrier.arrive.shared::cta.b64 _, [%0];" :: "r"(m) : "memory");
}
__device__ __forceinline__ void mbar_expect_tx(uint32_t m, uint32_t b) {
    asm volatile("mbarrier.arrive.expect_tx.shared::cta.b64 _, [%0], %1;"
                 :: "r"(m), "r"(b) : "memory");
}
__device__ __forceinline__ void mbar_wait(uint32_t m, uint32_t ph) {
    asm volatile(
        "{\n\t.reg .pred P;\n"
        "W_%=:\n\t"
        "mbarrier.try_wait.parity.acquire.cta.shared::cta.b64 P, [%0], %1, 0x989680;\n\t"
        "@P bra.uni D_%=;\n\t"
        "bra.uni W_%=;\n"
        "D_%=:\n\t}"
        :: "r"(m), "r"(ph) : "memory");
}
__device__ __forceinline__ void bulk_g2s(uint32_t dst, const void* src, uint32_t bytes,
                                         uint32_t mbar) {
    asm volatile(
        "cp.async.bulk.shared::cta.global.mbarrier::complete_tx::bytes [%0], [%1], %2, [%3];"
        :: "r"(dst), "l"(src), "r"(bytes), "r"(mbar) : "memory");
}
__device__ __forceinline__ void ldsm4(uint32_t& r0, uint32_t& r1, uint32_t& r2, uint32_t& r3,
                                      uint32_t a) {
    asm volatile("ldmatrix.sync.aligned.m8n8.x4.shared.b16 {%0,%1,%2,%3}, [%4];"
                 : "=r"(r0), "=r"(r1), "=r"(r2), "=r"(r3) : "r"(a));
}
__device__ __forceinline__ void mma_f16f32(float* d, const uint32_t* a, const uint32_t* b) {
    asm volatile(
        "mma.sync.aligned.m16n8k16.row.col.f32.f16.f16.f32 "
        "{%0,%1,%2,%3}, {%4,%5,%6,%7}, {%8,%9}, {%0,%1,%2,%3};"
        : "+f"(d[0]), "+f"(d[1]), "+f"(d[2]), "+f"(d[3])
        : "r"(a[0]), "r"(a[1]), "r"(a[2]), "r"(a[3]), "r"(b[0]), "r"(b[1]));
}
__device__ __forceinline__ void wait_flag(const uint32_t* f) {
    uint32_t v;
    do {
        asm volatile("ld.acquire.gpu.global.u32 %0, [%1];" : "=r"(v) : "l"(f) : "memory");
    } while (!v);
}

// ---------------- router ----------------
__global__ void router_kernel(const float* __restrict__ x, const float* __restrict__ Wr) {
    __shared__ float sx[D_MODEL];
    __shared__ float slog[NE];
    const int t = blockIdx.x, tid = threadIdx.x;
    const float* xr = x + (size_t)t * D_MODEL;
    for (int i = tid * 4; i < D_MODEL; i += 256 * 4)
        *(float4*)(sx + i) = *(const float4*)(xr + i);
    __syncthreads();
    const int w = tid >> 5, lane = tid & 31;
    const float* wr = Wr + (size_t)w * D_MODEL;
    float s = 0.f;
    for (int i = lane; i < D_MODEL; i += 32) s += sx[i] * wr[i];
    #pragma unroll
    for (int o = 16; o; o >>= 1) s += __shfl_xor_sync(0xffffffffu, s, o);
    if (lane == 0) slog[w] = s;
    __syncthreads();
    if (tid == 0) {
        float mx = slog[0]; int mi = 0;
        #pragma unroll
        for (int e = 1; e < NE; e++) if (slog[e] > mx) { mx = slog[e]; mi = e; }
        float sum = 0.f;
        #pragma unroll
        for (int e = 0; e < NE; e++) sum += expf(slog[e] - mx);
        g_idx[t] = mi;
        g_w[t] = 1.0f / sum;
    }
}

// ---------------- bucket + tile table + token map + counters + flag reset ------------
__global__ void bucket_kernel() {
    __shared__ int cnt[NE], off[NE], soff[NE], spo[NE + 1];
    const int tid = threadIdx.x;
    if (tid < NE) cnt[tid] = 0;
    __syncthreads();
    for (int t = tid; t < T_TOK; t += blockDim.x) atomicAdd(&cnt[g_idx[t]], 1);
    __syncthreads();
    if (tid == 0) {
        int acc = 0, pacc = 0, nt = 0;
        #pragma unroll
        for (int e = 0; e < NE; e++) {
            off[e] = acc; soff[e] = acc; g_off[e] = acc;
            spo[e] = pacc;
            int tiles = (cnt[e] + 127) >> 7;
            for (int i = 0; i < tiles; i++) {
                g_tile_e[nt] = e;
                g_tile_gt[nt] = (pacc >> 7) + i;
                g_tile_m64[nt] = (cnt[e] - i * 128) <= 64;
                nt++;
            }
            acc += cnt[e];
            pacc += tiles << 7;
        }
        g_off[NE] = acc;
        spo[NE] = pacc;
        g_ntiles = nt;
        g_work1 = 0;
        g_work2 = 0;
    }
    for (int i = tid; i < NT1 * NE * KT1; i += blockDim.x) g_f1[i] = 0;
    for (int i = tid; i < NT2 * NE * KT2; i += blockDim.x) g_f2[i] = 0;
    __syncthreads();
    for (int t = tid; t < T_TOK; t += blockDim.x) {
        int p = atomicAdd(&off[g_idx[t]], 1);
        g_order[p] = t;
    }
    __syncthreads();
    for (int p = tid; p < PM * 128; p += blockDim.x) {
        int tk = -1;
        #pragma unroll
        for (int e = 0; e < NE; e++)
            if (p >= spo[e] && p < spo[e] + cnt[e])
                tk = g_order[soff[e] + (p - spo[e])];
        g_ptok[p] = tk;
    }
}

// ---------------- prepass: gather x rows -> swizzled fp16 blocks ----------------
__global__ void __launch_bounds__(256) gather_a_kernel(const float* __restrict__ x) {
    const int gt = blockIdx.x, kt = blockIdx.y;
    const int tid = threadIdx.x;
    const int r = tid >> 1, half = tid & 1;
    const int tok = g_ptok[gt * 128 + r];
    uint32_t fw[16];
    if (tok >= 0) {
        const float4* src = (const float4*)(x + (size_t)tok * D_MODEL + kt * 64 + half * 32);
        #pragma unroll
        for (int q = 0; q < 8; q++) {
            float4 v = src[q];
            fw[q * 2]     = pack2h(v.x, v.y);
            fw[q * 2 + 1] = pack2h(v.z, v.w);
        }
    } else {
        #pragma unroll
        for (int q = 0; q < 16; q++) fw[q] = 0;
    }
    char* blk = g_A + ((size_t)gt * KT1 + kt) * BLKA;
    #pragma unroll
    for (int c = 0; c < 4; c++) {
        int ch = half * 4 + c;
        uint32_t off = (uint32_t)(r * 128) + (uint32_t)((ch ^ (r & 7)) << 4);
        *(uint4*)(blk + off) = ((uint4*)fw)[c];
    }
}

// ---------------- in-kernel weight conversion (helper warps) ----------------
// Unit = (nt, e, kt): 64 k-rows x 128 n-cols fp32 -> transposed swizzled fp16 block.
template <int NTD, int KT>
__device__ void convert_units(const float* __restrict__ W, char* __restrict__ Bdst,
                              uint32_t* __restrict__ flags, int ldb,
                              float* tb, int sid, int nstreams) {
    const int lane = threadIdx.x & 31;
    const int total = NTD * NE * KT;
    for (int u = sid; u < total; u += nstreams) {
        const int nt = u / (NE * KT);
        const int rem = u % (NE * KT);
        const int e = rem / KT;
        const int kt = rem % KT;
        const float* src = W + (size_t)e * D_MODEL * FF + (size_t)(kt * 64) * ldb + nt * 128;
        char* dst = Bdst + (((size_t)e * NTD + nt) * KT + kt) * BLKA;
        #pragma unroll 1
        for (int cn = 0; cn < 4; cn++) {
            #pragma unroll
            for (int i = 0; i < 16; i++) {
                int q = i * 32 + lane;
                int row = q >> 3, f4 = q & 7;
                *(float4*)(tb + row * 36 + f4 * 4) =
                    *(const float4*)(src + (size_t)row * ldb + cn * 32 + f4 * 4);
            }
            __syncwarp();
            const int r = cn * 32 + lane;
            uint32_t pk[32];
            #pragma unroll
            for (int j = 0; j < 32; j++)
                pk[j] = pack2h(tb[(2 * j) * 36 + lane], tb[(2 * j + 1) * 36 + lane]);
            #pragma unroll
            for (int ch = 0; ch < 8; ch++) {
                uint32_t off = (uint32_t)(r * 128) + (uint32_t)((ch ^ (r & 7)) << 4);
                *(uint4*)(dst + off) = make_uint4(pk[ch * 4], pk[ch * 4 + 1],
                                                  pk[ch * 4 + 2], pk[ch * 4 + 3]);
            }
            __syncwarp();
        }
        __threadfence();
        asm volatile("fence.proxy.async.global;" ::: "memory");
        __syncwarp();
        if (lane == 0)
            asm volatile("st.release.gpu.global.u32 [%0], %1;"
                         :: "l"(flags + u), "r"(1u) : "memory");
    }
}

// ---------------- persistent GEMM: consumers + producer + weight-convert helpers -----
#define ST_BYTES   32768u
#define SM_SLOT    98304           // 4 x int4 slot ring
#define SM_MBROFF  98368           // mfull 3x8 | mempty 3x8
#define SM_TB      98432           // 2 x (64x36 fp32 = 9216B) helper transpose buffers
#define SMEM_TOT   116864

template <int PHASE>
__global__ void __launch_bounds__(352, 1)
moe_gemm(const float* __restrict__ W, float* __restrict__ out) {
    constexpr int KT = (PHASE == 1) ? KT1 : KT2;
    constexpr int NTD = (PHASE == 1) ? NT1 : NT2;
    constexpr int LDB = (PHASE == 1) ? FF : D_MODEL;
    char* Bdst = (PHASE == 1) ? g_B1 : g_B2;
    uint32_t* flags = (PHASE == 1) ? g_f1 : g_f2;
    const int tid = threadIdx.x;
    const int wid = tid >> 5, lane = tid & 31;

    extern __shared__ char smem[];
    const uint32_t sb = s2u(smem);
    int4* slots = (int4*)(smem + SM_SLOT);
    const uint32_t mfull = sb + SM_MBROFF;
    const uint32_t mempty = sb + SM_MBROFF + 24;

    if (tid == 0) {
        #pragma unroll
        for (int i = 0; i < 3; i++) { mbar_init(mfull + i * 8, 1); mbar_init(mempty + i * 8, 8); }
    }
    __syncthreads();

    // ---------- helper warps 9,10: convert this GEMM's weights ----------
    if (wid >= 9) {
        float* tb = (float*)(smem + SM_TB + (wid - 9) * 9216);
        convert_units<NTD, KT>(W, Bdst, flags, LDB, tb,
                               blockIdx.x * 2 + (wid - 9), (int)gridDim.x * 2);
        return;
    }

    // ---------- producer warp 8: tile acquisition + flag-gated fills ----------
    if (wid == 8) {
        if (lane == 0) {
            const int ntl = g_ntiles;
            const int total = NTD * ntl;
            int f = 0;
            for (int seq = 0; ; seq++) {
                const int w = atomicAdd((PHASE == 1) ? &g_work1 : &g_work2, 1);
                int4 info;
                if (w >= total) {
                    info = make_int4(-1, 0, 0, 0);
                } else {
                    const int nt = w / ntl, tix = w % ntl;   // nt-major order
                    info = make_int4(nt, g_tile_e[tix], g_tile_gt[tix], g_tile_m64[tix]);
                }
                slots[seq & 3] = info;
                if (info.x < 0) {
                    const int s = f % 3;
                    if (f >= 3) mbar_wait(mempty + s * 8, ((f - 3) / 3) & 1);
                    mbar_arrive(mfull + s * 8);        // sentinel
                    break;
                }
                const char* srcA = (PHASE == 1) ? (g_A + (size_t)info.z * KT1 * BLKA)
                                                : (g_H + (size_t)info.z * KT2 * BLKA);
                const char* srcB = Bdst + (((size_t)info.y * NTD + info.x)) * KT * BLKA;
                const uint32_t* fl = flags + ((size_t)info.x * NE + info.y) * KT;
                for (int kt = 0; kt < KT; kt++, f++) {
                    const int s = f % 3;
                    if (f >= 3) mbar_wait(mempty + s * 8, ((f - 3) / 3) & 1);
                    wait_flag(fl + kt);
                    asm volatile("fence.proxy.async.global;" ::: "memory");
                    mbar_expect_tx(mfull + s * 8, ST_BYTES);
                    uint32_t dst = sb + (uint32_t)s * ST_BYTES;
                    bulk_g2s(dst,          srcA + (size_t)kt * BLKA, BLKA, mfull + s * 8);
                    bulk_g2s(dst + 16384u, srcB + (size_t)kt * BLKA, BLKA, mfull + s * 8);
                }
            }
        }
        return;
    }

    // ---------- consumer warps 0-7: wm in [0,2), wn in [0,4); warp tile 64x32 --------
    const int wm = wid >> 2, wn = wid & 3;
    const int lrA = (lane & 7) + ((lane >> 3) & 1) * 8;
    const int cA0 = lane >> 4;
    uint32_t a_off[4]; int a_rs[4];
    #pragma unroll
    for (int mf = 0; mf < 4; mf++) {
        int rr = wm * 64 + mf * 16 + lrA;
        a_off[mf] = (uint32_t)(rr * 128);
        a_rs[mf] = rr & 7;
    }
    const int lrB = (lane & 7) + ((lane >> 4) << 3);
    const int cB0 = (lane >> 3) & 1;
    uint32_t b_off[2]; int b_rs[2];
    #pragma unroll
    for (int p = 0; p < 2; p++) {
        int rr = wn * 32 + p * 16 + lrB;
        b_off[p] = (uint32_t)(rr * 128);
        b_rs[p] = rr & 7;
    }

    int c = 0;
    for (int seq = 0; ; seq++) {
        {
            const int s0 = c % 3;
            mbar_wait(mfull + s0 * 8, (c / 3) & 1);
        }
        const int4 info = slots[seq & 3];
        if (info.x < 0) break;
        const int nt = info.x, gt = info.z;
        const bool skipw = (info.w && wm == 1);

        int mytok[8];
        float mywv[8];
        if (PHASE == 2 && !skipw) {
            #pragma unroll
            for (int mf = 0; mf < 4; mf++)
                #pragma unroll
                for (int hh = 0; hh < 2; hh++) {
                    const int rl = wm * 64 + mf * 16 + hh * 8 + (lane >> 2);
                    const int tk = g_ptok[gt * 128 + rl];
                    mytok[mf * 2 + hh] = tk;
                    mywv[mf * 2 + hh] = (tk >= 0) ? g_w[tk] : 0.f;
                }
        }

        float acc[4][4][4];
        #pragma unroll
        for (int i = 0; i < 4; i++)
            #pragma unroll
            for (int j = 0; j < 4; j++)
                #pragma unroll
                for (int q = 0; q < 4; q++) acc[i][j][q] = 0.f;

        for (int kt = 0; kt < KT; kt++) {
            const int s = c % 3;
            if (kt > 0) mbar_wait(mfull + s * 8, (c / 3) & 1);
            if (!skipw) {
                const uint32_t stA = sb + (uint32_t)s * ST_BYTES;
                const uint32_t stB = stA + 16384u;
                #pragma unroll
                for (int ks = 0; ks < 4; ks++) {
                    uint32_t af[16], bf[8];
                    const int cA = cA0 + ks * 2;
                    #pragma unroll
                    for (int mf = 0; mf < 4; mf++) {
                        uint32_t o = a_off[mf] + (uint32_t)((cA ^ a_rs[mf]) << 4);
                        ldsm4(af[mf*4], af[mf*4+1], af[mf*4+2], af[mf*4+3], stA + o);
                    }
                    const int cB = cB0 + ks * 2;
                    #pragma unroll
                    for (int p = 0; p < 2; p++) {
                        uint32_t o = b_off[p] + (uint32_t)((cB ^ b_rs[p]) << 4);
                        ldsm4(bf[p*4], bf[p*4+1], bf[p*4+2], bf[p*4+3], stB + o);
                    }
                    #pragma unroll
                    for (int mf = 0; mf < 4; mf++)
                        #pragma unroll
                        for (int nf = 0; nf < 4; nf++)
                            mma_f16f32(acc[mf][nf], &af[mf * 4],
                                       &bf[(nf >> 1) * 4 + (nf & 1) * 2]);
                }
            }
            if (lane == 0) mbar_arrive(mempty + s * 8);
            c++;
        }

        // ---------------- direct epilogue ----------------
        if (!skipw) {
            #pragma unroll
            for (int mf = 0; mf < 4; mf++)
                #pragma unroll
                for (int nf = 0; nf < 4; nf++) {
                    const float* cc = acc[mf][nf];
                    const int rbase = wm * 64 + mf * 16 + (lane >> 2);
                    const int ncol = nt * 128 + wn * 32 + nf * 8 + (lane & 3) * 2;
                    #pragma unroll
                    for (int hh = 0; hh < 2; hh++) {
                        const int rl = rbase + hh * 8;
                        if (PHASE == 1) {
                            float v0 = gelu_exact(cc[hh * 2]);
                            float v1 = gelu_exact(cc[hh * 2 + 1]);
                            const int kt2 = ncol >> 6, kl = ncol & 63;
                            char* blk = g_H + ((size_t)gt * KT2 + kt2) * BLKA;
                            uint32_t off = (uint32_t)(rl * 128)
                                         + (uint32_t)((((kl >> 3) ^ (rl & 7)) << 4)
                                                      + (kl & 7) * 2);
                            *(uint32_t*)(blk + off) = pack2h(v0, v1);
                        } else {
                            const int tk = mytok[mf * 2 + hh];
                            if (tk < 0) continue;
                            const float wv = mywv[mf * 2 + hh];
                            float2 o = make_float2(cc[hh * 2] * wv, cc[hh * 2 + 1] * wv);
                            *(float2*)(out + (size_t)tk * D_MODEL + ncol) = o;
                        }
                    }
                }
        }
    }
}

// ---------------- launch ----------------
extern "C" void kernel_launch(void* const* d_in, const int* in_sizes, int n_in,
                              void* d_out, int out_size) {
    const float* x  = (const float*)d_in[0];
    const float* Wr = (const float*)d_in[1];
    const float* W1 = (const float*)d_in[2];
    const float* W2 = (const float*)d_in[3];
    float* out = (float*)d_out;

    cudaFuncSetAttribute(moe_gemm<1>, cudaFuncAttributeMaxDynamicSharedMemorySize, SMEM_TOT);
    cudaFuncSetAttribute(moe_gemm<2>, cudaFuncAttributeMaxDynamicSharedMemorySize, SMEM_TOT);

    router_kernel<<<T_TOK, 256>>>(x, Wr);
    bucket_kernel<<<1, 1024>>>();
    gather_a_kernel<<<dim3(PM, KT1), 256>>>(x);
    moe_gemm<1><<<NBLK, 352, SMEM_TOT>>>(W1, nullptr);
    moe_gemm<2><<<NBLK, 352, SMEM_TOT>>>(W2, out);
}